// round 9
// baseline (speedup 1.0000x reference)
#include <cuda_runtime.h>
#include <math.h>

#define BATCH   32
#define LAYERS  32
#define DIM     4096
#define SELK    24
#define NCHOICE 9
#define GS_EPS  1e-10f

#define F4_PER_LAYER (DIM / 4)      // 1024 float4 per layer

// Block = one (batch, layer). Per-warp Gumbel argmax (no barrier), then the
// whole block either copies its layer (if it falls in [idx, idx+24)) or exits.
// Load addresses depend only on l, never on idx — idx gates only the
// predicate, so traffic is the 12 MB read + 12 MB write floor while keeping
// R8's high-occupancy overlap. Streaming stores keep the input L2-resident.

__global__ void __launch_bounds__(256)
fused_kernel(const float4* __restrict__ feats4,
             const float*  __restrict__ logits,
             const float*  __restrict__ noise,
             float* __restrict__ out) {
    const int b = blockIdx.y;
    const int l = blockIdx.x;             // layer 0..31
    const int t = threadIdx.x;
    const int lane = t & 31;

    // ---- per-warp Gumbel argmax (lanes 0-8): L2-hot load + shuffle reduce ----
    float v  = -INFINITY;
    int   bc = lane;
    if (lane < NCHOICE) {
        float u = __ldg(&noise[b * NCHOICE + lane]);
        float g = -logf(-logf(u + GS_EPS) + GS_EPS);
        v = __ldg(&logits[lane]) + g;     // tau=1; softmax monotone -> same argmax
    }
    #pragma unroll
    for (int off = 16; off; off >>= 1) {
        float ov = __shfl_down_sync(0xffffffffu, v,  off);
        int   oc = __shfl_down_sync(0xffffffffu, bc, off);
        if (ov > v || (ov == v && oc < bc)) { v = ov; bc = oc; }  // first-max wins
    }
    const int idx = __shfl_sync(0xffffffffu, bc, 0);

    // one-hot selection_probs tail (one block per batch)
    if (l == 0 && t < NCHOICE) {
        out[(size_t)BATCH * SELK * DIM + b * NCHOICE + t] =
            (t == idx) ? 1.0f : 0.0f;
    }

    // ---- window predicate: out-of-window blocks exit, no feature traffic ----
    const unsigned rel = (unsigned)(l - idx);
    if (rel >= SELK) return;

    const float4* __restrict__ src =
        feats4 + ((size_t)b * LAYERS + l) * F4_PER_LAYER;
    float4* __restrict__ dst =
        (float4*)out + ((size_t)b * SELK + rel) * F4_PER_LAYER;

    // 4 independent LDG.128, then 4 streaming STG.128
    float4 v0 = __ldg(&src[t]);
    float4 v1 = __ldg(&src[t + 256]);
    float4 v2 = __ldg(&src[t + 512]);
    float4 v3 = __ldg(&src[t + 768]);

    __stcs(&dst[t],       v0);
    __stcs(&dst[t + 256], v1);
    __stcs(&dst[t + 512], v2);
    __stcs(&dst[t + 768], v3);
}

extern "C" void kernel_launch(void* const* d_in, const int* in_sizes, int n_in,
                              void* d_out, int out_size) {
    const float* feats  = (const float*)d_in[0];
    const float* logits = (const float*)d_in[1];
    const float* noise  = (const float*)d_in[2];
    float*       out    = (float*)d_out;

    dim3 grid(LAYERS, BATCH);             // 1024 blocks, one per (layer, batch)
    fused_kernel<<<grid, 256>>>((const float4*)feats, logits, noise, out);
}

// round 10
// speedup vs baseline: 1.0941x; 1.0941x over previous
#include <cuda_runtime.h>
#include <math.h>

#define BATCH   32
#define LAYERS  32
#define DIM     4096
#define SELK    24
#define NCHOICE 9
#define GS_EPS  1e-10f

#define F4_PER_LAYER (DIM / 4)      // 1024 float4 per layer

// Floor-traffic kernel: 12 MB read + 12 MB write, nothing else.
// Block = one (batch, layer) via 1D grid. Per-warp Gumbel argmax (shuffle
// reduce, no barrier, overlapped); load addresses depend only on l — idx
// gates only the store predicate, so out-of-window blocks exit with zero
// feature traffic. Streaming stores keep the input L2-resident across
// graph replays. Measured at the platform's effective L2-path cap.

__global__ void __launch_bounds__(256)
fused_kernel(const float4* __restrict__ feats4,
             const float*  __restrict__ logits,
             const float*  __restrict__ noise,
             float* __restrict__ out) {
    const int bid = blockIdx.x;
    const int b = bid >> 5;               // batch 0..31
    const int l = bid & 31;               // layer 0..31
    const int t = threadIdx.x;
    const int lane = t & 31;

    // ---- per-warp Gumbel argmax (lanes 0-8): L2-hot load + shuffle reduce ----
    float v  = -INFINITY;
    int   bc = lane;
    if (lane < NCHOICE) {
        float u = __ldg(&noise[b * NCHOICE + lane]);
        float g = -logf(-logf(u + GS_EPS) + GS_EPS);
        v = __ldg(&logits[lane]) + g;     // tau=1; softmax monotone -> same argmax
    }
    #pragma unroll
    for (int off = 16; off; off >>= 1) {
        float ov = __shfl_down_sync(0xffffffffu, v,  off);
        int   oc = __shfl_down_sync(0xffffffffu, bc, off);
        if (ov > v || (ov == v && oc < bc)) { v = ov; bc = oc; }  // first-max wins
    }
    const int idx = __shfl_sync(0xffffffffu, bc, 0);

    // one-hot selection_probs tail (one block per batch)
    if (l == 0 && t < NCHOICE) {
        out[(size_t)BATCH * SELK * DIM + b * NCHOICE + t] =
            (t == idx) ? 1.0f : 0.0f;
    }

    // ---- window predicate: out-of-window blocks exit, zero feature traffic ----
    const unsigned rel = (unsigned)(l - idx);
    if (rel >= SELK) return;

    const float4* __restrict__ src =
        feats4 + ((size_t)b * LAYERS + l) * F4_PER_LAYER;
    float4* __restrict__ dst =
        (float4*)out + ((size_t)b * SELK + rel) * F4_PER_LAYER;

    // 4 independent LDG.128, then 4 streaming STG.128
    float4 v0 = __ldg(&src[t]);
    float4 v1 = __ldg(&src[t + 256]);
    float4 v2 = __ldg(&src[t + 512]);
    float4 v3 = __ldg(&src[t + 768]);

    __stcs(&dst[t],       v0);
    __stcs(&dst[t + 256], v1);
    __stcs(&dst[t + 512], v2);
    __stcs(&dst[t + 768], v3);
}

extern "C" void kernel_launch(void* const* d_in, const int* in_sizes, int n_in,
                              void* d_out, int out_size) {
    const float* feats  = (const float*)d_in[0];
    const float* logits = (const float*)d_in[1];
    const float* noise  = (const float*)d_in[2];
    float*       out    = (float*)d_out;

    fused_kernel<<<BATCH * LAYERS, 256>>>((const float4*)feats, logits, noise, out);
}